// round 14
// baseline (speedup 1.0000x reference)
#include <cuda_runtime.h>

#define HIDDEN 32
#define FEAT 30
#define NK 29                 /* feature 29 (mask bit) folded into bias */
#define TSTEPS 512
#define BATCH 4096
#define CHUNK 32
#define XROW 18               /* xsd ull row stride: 16B-aligned, <=4-way STS */
#define TSF (TSTEPS * FEAT)

typedef unsigned long long ull;

// Scratch: XG[b][t][j] = (if, go) fp32 gate partials (x-part + bias); mask[b][t].
__device__ ulonglong2 g_xg[(size_t)BATCH * TSTEPS * HIDDEN];
__device__ float g_mask[(size_t)BATCH * TSTEPS];

__device__ __forceinline__ float tanhap(float x) {
    float y; asm("tanh.approx.f32 %0, %1;" : "=f"(y) : "f"(x)); return y;
}
__device__ __forceinline__ float sigf(float x) {
    return fmaf(0.5f, tanhap(0.5f * x), 0.5f);
}
__device__ __forceinline__ ull fma2(ull a, ull b, ull c) {
    ull d;
    asm("fma.rn.f32x2 %0, %1, %2, %3;" : "=l"(d) : "l"(a), "l"(b), "l"(c));
    return d;
}
__device__ __forceinline__ ull pack2(float lo, float hi) {
    ull d; asm("mov.b64 %0, {%1, %2};" : "=l"(d) : "f"(lo), "f"(hi)); return d;
}
__device__ __forceinline__ ull dup2(float v) {
    ull d; asm("mov.b64 %0, {%1, %1};" : "=l"(d) : "f"(v)); return d;
}
__device__ __forceinline__ float2 unpack2(ull v) {
    float lo, hi; asm("mov.b64 {%0, %1}, %2;" : "=f"(lo), "=f"(hi) : "l"(v));
    return make_float2(lo, hi);
}

// ========================== K1: dense x-gates ==============================
// Block = 8 warps, one sample. Warp covers 64 timesteps in 4 iters of 16.
// W_ih register-resident; staging rows padded (XROW) for conflict-free-ish STS.
__global__ void __launch_bounds__(256)
xgate_kernel(const float* __restrict__ x,
             const float* __restrict__ W_ih,
             const float* __restrict__ b_ih, const float* __restrict__ b_hh)
{
    __shared__ ull xsd[8][NK][XROW];          // [warp][k][t] dup'd x values

    const int tid  = threadIdx.x;
    const int lane = tid & 31;
    const int wid  = tid >> 5;
    const int b    = blockIdx.x;

    // Weights register-resident, loop-invariant (29 ulonglong2 = 116 regs).
    ulonglong2 wr[NK];
    #pragma unroll
    for (int k = 0; k < NK; ++k) {
        wr[k] = make_ulonglong2(
            pack2(W_ih[lane * FEAT + k],        W_ih[(32 + lane) * FEAT + k]),
            pack2(W_ih[(64 + lane) * FEAT + k], W_ih[(96 + lane) * FEAT + k]));
    }
    // Bias with mask-bit column (W_ih[:,29] * 1.0) folded in.
    const ull bias_if = pack2(
        b_ih[lane]      + b_hh[lane]      + W_ih[lane * FEAT + 29],
        b_ih[32 + lane] + b_hh[32 + lane] + W_ih[(32 + lane) * FEAT + 29]);
    const ull bias_go = pack2(
        b_ih[64 + lane] + b_hh[64 + lane] + W_ih[(64 + lane) * FEAT + 29],
        b_ih[96 + lane] + b_hh[96 + lane] + W_ih[(96 + lane) * FEAT + 29]);

    const float* xb = x + (size_t)b * TSF;

    #pragma unroll 1
    for (int iter = 0; iter < 4; ++iter) {
        const int t0 = wid * 64 + iter * 16;

        // Stage 16 timesteps (480 floats, coalesced LDG); mask column -> g_mask.
        #pragma unroll
        for (int r = 0; r < 15; ++r) {
            const int idx = r * 32 + lane;          // 0..479
            const int tr = idx / FEAT, k = idx % FEAT;
            const float v = xb[(size_t)t0 * FEAT + idx];
            if (k < NK) xsd[wid][k][tr] = dup2(v);
            else        g_mask[(size_t)b * TSTEPS + t0 + tr] = v;
        }
        __syncwarp();

        // Two passes of 8 timesteps (keeps live accumulators at 32 regs).
        #pragma unroll
        for (int half = 0; half < 2; ++half) {
            ull aif[8], ago[8];
            #pragma unroll
            for (int t = 0; t < 8; ++t) { aif[t] = bias_if; ago[t] = bias_go; }

            #pragma unroll
            for (int k = 0; k < NK; ++k) {
                const ulonglong2 w = wr[k];
                const ulonglong2* xr =
                    reinterpret_cast<const ulonglong2*>(&xsd[wid][k][half * 8]);
                #pragma unroll
                for (int p = 0; p < 4; ++p) {
                    const ulonglong2 xp = xr[p];    // dup'd (x_t), (x_t+1)
                    aif[2 * p]     = fma2(xp.x, w.x, aif[2 * p]);
                    ago[2 * p]     = fma2(xp.x, w.y, ago[2 * p]);
                    aif[2 * p + 1] = fma2(xp.y, w.x, aif[2 * p + 1]);
                    ago[2 * p + 1] = fma2(xp.y, w.y, ago[2 * p + 1]);
                }
            }
            #pragma unroll
            for (int t = 0; t < 8; ++t)
                g_xg[((size_t)b * TSTEPS + t0 + half * 8 + t) * HIDDEN + lane] =
                    make_ulonglong2(aif[t], ago[t]);
        }
        __syncwarp();
    }
}

// ========================== K2: recurrence (NS=2) ==========================
struct Smem2 {
    ull hq[2][HIDDEN][6];       // [buf][k][0..1 used] dup'd h; 48B rows, aligned
    ull hist[CHUNK][33];        // [slot][j] pack2(hs0, hs1), 2-way worst
    ull wcd0[HIDDEN], wcd1[HIDDEN], wcdl[HIDDEN];
};

__global__ void __launch_bounds__(32)
lstm_rec_kernel(const float* __restrict__ h0, const float* __restrict__ c0,
                const float* __restrict__ W_hh,
                const float* __restrict__ W_all, const float* __restrict__ b_all,
                const float* __restrict__ W_pos, const float* __restrict__ b_pos,
                const float* __restrict__ W_lv, const float* __restrict__ b_lv,
                float* __restrict__ out)
{
    __shared__ Smem2 sm;
    const int lane = threadIdx.x;
    const int s0 = blockIdx.x * 2;

    ull whh_if[HIDDEN], whh_go[HIDDEN];     // register-resident
    #pragma unroll
    for (int k = 0; k < HIDDEN; ++k) {
        whh_if[k] = pack2(W_hh[lane * HIDDEN + k],        W_hh[(32 + lane) * HIDDEN + k]);
        whh_go[k] = pack2(W_hh[(64 + lane) * HIDDEN + k], W_hh[(96 + lane) * HIDDEN + k]);
    }
    // Folded heads: wc = W_pos @ W_all, cb = W_pos @ b_all + b_pos.
    float wc0 = 0.f, wc1 = 0.f, cb0 = b_pos[0], cb1 = b_pos[1];
    #pragma unroll
    for (int m = 0; m < HIDDEN; ++m) {
        const float wa = W_all[m * HIDDEN + lane];
        wc0 = fmaf(W_pos[m],      wa, wc0);
        wc1 = fmaf(W_pos[32 + m], wa, wc1);
        cb0 = fmaf(W_pos[m],      b_all[m], cb0);
        cb1 = fmaf(W_pos[32 + m], b_all[m], cb1);
    }
    sm.wcd0[lane] = dup2(wc0);
    sm.wcd1[lane] = dup2(wc1);
    sm.wcdl[lane] = dup2(W_lv[lane]);
    const float blv = b_lv[0];

    float h0r = h0[s0 * HIDDEN + lane],       c0r = c0[s0 * HIDDEN + lane];
    float h1r = h0[(s0 + 1) * HIDDEN + lane], c1r = c0[(s0 + 1) * HIDDEN + lane];

    *reinterpret_cast<ulonglong2*>(&sm.hq[0][lane][0]) =
        make_ulonglong2(dup2(h0r), dup2(h1r));

    // Streaming pointers (incremented per step; no per-step 64-bit mults).
    const ulonglong2* xg0 = g_xg + (size_t)s0 * TSTEPS * HIDDEN + lane;
    const ulonglong2* xg1 = xg0 + (size_t)TSTEPS * HIDDEN;
    const float* mp0 = g_mask + (size_t)s0 * TSTEPS;
    const float* mp1 = mp0 + TSTEPS;

    ulonglong2 xgp0 = xg0[0], xgp1 = xg1[0];
    float mk0 = mp0[0], mk1 = mp1[0];
    __syncwarp();

    float* pos_out = out;                                   // [B,T,2]
    float* lv_out  = out + (size_t)BATCH * TSTEPS * 2;      // [B,T,1]
    float* hT_out  = out + (size_t)BATCH * TSTEPS * 3;      // [1,B,H]
    float* cT_out  = hT_out + BATCH * HIDDEN;               // [1,B,H]

    for (int t = 0; t < TSTEPS; ++t) {
        const int bsel = t & 1;
        const int slot = t & (CHUNK - 1);

        // Prefetch next step (clamped at tail to avoid OOB).
        const int go = (t + 1 < TSTEPS) ? HIDDEN : 0;
        const int mo = (t + 1 < TSTEPS) ? 1 : 0;
        const ulonglong2 xgn0 = xg0[go], xgn1 = xg1[go];
        const float mn0 = mp0[mo], mn1 = mp1[mo];

        // Gates = xg + h @ W_hh (weights in registers).
        ull aif0 = xgp0.x, ago0 = xgp0.y;
        ull aif1 = xgp1.x, ago1 = xgp1.y;
        #pragma unroll
        for (int k = 0; k < HIDDEN; ++k) {
            const ulonglong2 hk =
                *reinterpret_cast<const ulonglong2*>(&sm.hq[bsel][k][0]);
            const ull wi = whh_if[k], wg = whh_go[k];
            aif0 = fma2(hk.x, wi, aif0); ago0 = fma2(hk.x, wg, ago0);
            aif1 = fma2(hk.y, wi, aif1); ago1 = fma2(hk.y, wg, ago1);
        }

        float hs0, hs1;
        {
            const bool act = (mk0 == 1.0f);
            const float2 g1 = unpack2(aif0), g2 = unpack2(ago0);
            const float cn = fmaf(sigf(g1.y), c0r, sigf(g1.x) * tanhap(g2.x));
            const float hn = sigf(g2.y) * tanhap(cn);
            c0r = act ? cn : c0r; h0r = act ? hn : h0r; hs0 = act ? hn : 0.f;
        }
        {
            const bool act = (mk1 == 1.0f);
            const float2 g1 = unpack2(aif1), g2 = unpack2(ago1);
            const float cn = fmaf(sigf(g1.y), c1r, sigf(g1.x) * tanhap(g2.x));
            const float hn = sigf(g2.y) * tanhap(cn);
            c1r = act ? cn : c1r; h1r = act ? hn : h1r; hs1 = act ? hn : 0.f;
        }

        *reinterpret_cast<ulonglong2*>(&sm.hq[bsel ^ 1][lane][0]) =
            make_ulonglong2(dup2(h0r), dup2(h1r));
        sm.hist[slot][lane] = pack2(hs0, hs1);
        __syncwarp();

        // Bulk head phase over the finished 32-step chunk (all lanes busy).
        if (slot == CHUNK - 1) {
            const int tt = lane;
            const ull* hb = &sm.hist[tt][0];
            ull p0 = 0ULL, p1 = 0ULL, pl = 0ULL;
            #pragma unroll
            for (int j = 0; j < HIDDEN; ++j) {
                const ull hv = hb[j];
                p0 = fma2(hv, sm.wcd0[j], p0);
                p1 = fma2(hv, sm.wcd1[j], p1);
                pl = fma2(hv, sm.wcdl[j], pl);
            }
            const float2 q0 = unpack2(p0), q1 = unpack2(p1), ql = unpack2(pl);
            const int tg = t - (CHUNK - 1) + tt;
            const size_t oA = (size_t)s0 * TSTEPS + tg;
            const size_t oB = oA + TSTEPS;
            reinterpret_cast<float2*>(pos_out)[oA] = make_float2(q0.x + cb0, q1.x + cb1);
            reinterpret_cast<float2*>(pos_out)[oB] = make_float2(q0.y + cb0, q1.y + cb1);
            lv_out[oA] = sigf(ql.x + blv);
            lv_out[oB] = sigf(ql.y + blv);
            __syncwarp();
        }

        xgp0 = xgn0; xgp1 = xgn1; mk0 = mn0; mk1 = mn1;
        xg0 += go; xg1 += go; mp0 += mo; mp1 += mo;
    }

    hT_out[s0 * HIDDEN + lane]       = h0r;
    hT_out[(s0 + 1) * HIDDEN + lane] = h1r;
    cT_out[s0 * HIDDEN + lane]       = c0r;
    cT_out[(s0 + 1) * HIDDEN + lane] = c1r;
}

extern "C" void kernel_launch(void* const* d_in, const int* in_sizes, int n_in,
                              void* d_out, int out_size)
{
    const float* x    = (const float*)d_in[0];
    const float* h0   = (const float*)d_in[1];
    const float* c0   = (const float*)d_in[2];
    const float* W_ih = (const float*)d_in[3];
    const float* W_hh = (const float*)d_in[4];
    const float* b_ih = (const float*)d_in[5];
    const float* b_hh = (const float*)d_in[6];
    const float* W_all= (const float*)d_in[7];
    const float* b_all= (const float*)d_in[8];
    const float* W_pos= (const float*)d_in[9];
    const float* b_pos= (const float*)d_in[10];
    const float* W_lv = (const float*)d_in[11];
    const float* b_lv = (const float*)d_in[12];
    float* out = (float*)d_out;

    xgate_kernel<<<BATCH, 256>>>(x, W_ih, b_ih, b_hh);
    lstm_rec_kernel<<<BATCH / 2, 32>>>(h0, c0, W_hh,
                                       W_all, b_all, W_pos, b_pos, W_lv, b_lv, out);
}

// round 15
// speedup vs baseline: 1.2707x; 1.2707x over previous
#include <cuda_runtime.h>

#define HIDDEN 32
#define FEAT 30
#define NK 29                 /* feature 29 (mask bit) folded into bias */
#define TSTEPS 512
#define BATCH 4096
#define CHUNK 16
#define K1TS 8                /* timesteps staged per K1 inner iter */
#define XROW 10               /* xsd ull row stride: 80B, 16B-aligned */
#define TSF (TSTEPS * FEAT)

typedef unsigned long long ull;

// Scratch: XG[b][t][j] = (if, go) fp32 gate partials (x-part + bias); mask[b][t].
__device__ ulonglong2 g_xg[(size_t)BATCH * TSTEPS * HIDDEN];
__device__ float g_mask[(size_t)BATCH * TSTEPS];

__device__ __forceinline__ float tanhap(float x) {
    float y; asm("tanh.approx.f32 %0, %1;" : "=f"(y) : "f"(x)); return y;
}
__device__ __forceinline__ float sigf(float x) {
    return fmaf(0.5f, tanhap(0.5f * x), 0.5f);
}
__device__ __forceinline__ ull fma2(ull a, ull b, ull c) {
    ull d;
    asm("fma.rn.f32x2 %0, %1, %2, %3;" : "=l"(d) : "l"(a), "l"(b), "l"(c));
    return d;
}
__device__ __forceinline__ ull pack2(float lo, float hi) {
    ull d; asm("mov.b64 %0, {%1, %2};" : "=l"(d) : "f"(lo), "f"(hi)); return d;
}
__device__ __forceinline__ ull dup2(float v) {
    ull d; asm("mov.b64 %0, {%1, %1};" : "=l"(d) : "f"(v)); return d;
}
__device__ __forceinline__ float2 unpack2(ull v) {
    float lo, hi; asm("mov.b64 {%0, %1}, %2;" : "=f"(lo), "=f"(hi) : "l"(v));
    return make_float2(lo, hi);
}

// ========================== K1: dense x-gates ==============================
// Block = 8 warps, one sample. Register-capped (<=85) so nothing spills;
// weights live in conflict-free smem, amortized over 8 staged timesteps.
__global__ void __launch_bounds__(256, 3)
xgate_kernel(const float* __restrict__ x,
             const float* __restrict__ W_ih,
             const float* __restrict__ b_ih, const float* __restrict__ b_hh)
{
    __shared__ ulonglong2 sWih[NK][HIDDEN];   // [k][j]: 512B rows, conflict-free
    __shared__ ull xsd[8][NK][XROW];          // [warp][k][t] dup'd x values

    const int tid  = threadIdx.x;
    const int lane = tid & 31;
    const int wid  = tid >> 5;
    const int b    = blockIdx.x;

    for (int idx = tid; idx < NK * HIDDEN; idx += 256) {
        const int k = idx >> 5, j = idx & 31;
        sWih[k][j] = make_ulonglong2(
            pack2(W_ih[j * FEAT + k],        W_ih[(32 + j) * FEAT + k]),
            pack2(W_ih[(64 + j) * FEAT + k], W_ih[(96 + j) * FEAT + k]));
    }
    // Bias with mask-bit column (W_ih[:,29] * 1.0) folded in.
    const ull bias_if = pack2(
        b_ih[lane]      + b_hh[lane]      + W_ih[lane * FEAT + 29],
        b_ih[32 + lane] + b_hh[32 + lane] + W_ih[(32 + lane) * FEAT + 29]);
    const ull bias_go = pack2(
        b_ih[64 + lane] + b_hh[64 + lane] + W_ih[(64 + lane) * FEAT + 29],
        b_ih[96 + lane] + b_hh[96 + lane] + W_ih[(96 + lane) * FEAT + 29]);
    __syncthreads();

    const float* xb = x + (size_t)b * TSF;

    #pragma unroll 1
    for (int iter = 0; iter < TSTEPS / (8 * K1TS); ++iter) {
        const int t0 = wid * (TSTEPS / 8) + iter * K1TS;

        // Stage 8 timesteps (240 floats, coalesced); mask column -> g_mask.
        #pragma unroll
        for (int r = 0; r < 8; ++r) {
            const int idx = r * 32 + lane;           // 0..255 (240 used)
            if (idx < K1TS * FEAT) {
                const int tr = idx / FEAT, k = idx % FEAT;
                const float v = xb[(size_t)t0 * FEAT + idx];
                if (k < NK) xsd[wid][k][tr] = dup2(v);
                else        g_mask[(size_t)b * TSTEPS + t0 + tr] = v;
            }
        }
        __syncwarp();

        ull aif[K1TS], ago[K1TS];
        #pragma unroll
        for (int t = 0; t < K1TS; ++t) { aif[t] = bias_if; ago[t] = bias_go; }

        #pragma unroll
        for (int k = 0; k < NK; ++k) {
            const ulonglong2 w = sWih[k][lane];      // lane-distinct LDS.128
            const ulonglong2* xr =
                reinterpret_cast<const ulonglong2*>(&xsd[wid][k][0]);
            #pragma unroll
            for (int p = 0; p < K1TS / 2; ++p) {
                const ulonglong2 xp = xr[p];         // broadcast: dup'd x_t, x_t+1
                aif[2 * p]     = fma2(xp.x, w.x, aif[2 * p]);
                ago[2 * p]     = fma2(xp.x, w.y, ago[2 * p]);
                aif[2 * p + 1] = fma2(xp.y, w.x, aif[2 * p + 1]);
                ago[2 * p + 1] = fma2(xp.y, w.y, ago[2 * p + 1]);
            }
        }
        #pragma unroll
        for (int t = 0; t < K1TS; ++t)
            g_xg[((size_t)b * TSTEPS + t0 + t) * HIDDEN + lane] =
                make_ulonglong2(aif[t], ago[t]);
        __syncwarp();
    }
}

// ========================== K2: recurrence (NS=4, depth-2 prefetch) ========
struct Smem2 {
    ull hq[2][HIDDEN][6];          // [buf][k][s(0..3)+pad] dup'd h; 48B rows
    ulonglong2 hist[CHUNK][33];    // [slot][j] masked-h pairs, padded
    ull wcd0[HIDDEN], wcd1[HIDDEN], wcdl[HIDDEN];
};

__global__ void __launch_bounds__(32)
lstm_rec_kernel(const float* __restrict__ h0, const float* __restrict__ c0,
                const float* __restrict__ W_hh,
                const float* __restrict__ W_all, const float* __restrict__ b_all,
                const float* __restrict__ W_pos, const float* __restrict__ b_pos,
                const float* __restrict__ W_lv, const float* __restrict__ b_lv,
                float* __restrict__ out)
{
    __shared__ Smem2 sm;
    const int lane = threadIdx.x;
    const int s0 = blockIdx.x * 4;

    ull whh_if[HIDDEN], whh_go[HIDDEN];   // register-resident
    #pragma unroll
    for (int k = 0; k < HIDDEN; ++k) {
        whh_if[k] = pack2(W_hh[lane * HIDDEN + k],        W_hh[(32 + lane) * HIDDEN + k]);
        whh_go[k] = pack2(W_hh[(64 + lane) * HIDDEN + k], W_hh[(96 + lane) * HIDDEN + k]);
    }
    // Folded heads: wc = W_pos @ W_all, cb = W_pos @ b_all + b_pos.
    float wc0 = 0.f, wc1 = 0.f, cb0 = b_pos[0], cb1 = b_pos[1];
    #pragma unroll
    for (int m = 0; m < HIDDEN; ++m) {
        const float wa = W_all[m * HIDDEN + lane];
        wc0 = fmaf(W_pos[m],      wa, wc0);
        wc1 = fmaf(W_pos[32 + m], wa, wc1);
        cb0 = fmaf(W_pos[m],      b_all[m], cb0);
        cb1 = fmaf(W_pos[32 + m], b_all[m], cb1);
    }
    sm.wcd0[lane] = dup2(wc0);
    sm.wcd1[lane] = dup2(wc1);
    sm.wcdl[lane] = dup2(W_lv[lane]);
    const float blv = b_lv[0];

    float h[4], c[4];
    #pragma unroll
    for (int s = 0; s < 4; ++s) {
        h[s] = h0[(s0 + s) * HIDDEN + lane];
        c[s] = c0[(s0 + s) * HIDDEN + lane];
    }
    {
        ulonglong2* hw = reinterpret_cast<ulonglong2*>(&sm.hq[0][lane][0]);
        hw[0] = make_ulonglong2(dup2(h[0]), dup2(h[1]));
        hw[1] = make_ulonglong2(dup2(h[2]), dup2(h[3]));
    }

    // Streaming pointers, pre-advanced for depth-2 prefetch.
    const ulonglong2* xp[4];
    const float* mp[4];
    ulonglong2 xbuf[2][4];
    float mbuf[2][4];
    #pragma unroll
    for (int s = 0; s < 4; ++s) {
        const ulonglong2* base = g_xg + (size_t)(s0 + s) * TSTEPS * HIDDEN + lane;
        const float* mbase = g_mask + (size_t)(s0 + s) * TSTEPS;
        xbuf[0][s] = base[0];           mbuf[0][s] = mbase[0];
        xbuf[1][s] = base[HIDDEN];      mbuf[1][s] = mbase[1];
        xp[s] = base + 2 * HIDDEN;      mp[s] = mbase + 2;
    }
    __syncwarp();

    float* pos_out = out;                                   // [B,T,2]
    float* lv_out  = out + (size_t)BATCH * TSTEPS * 2;      // [B,T,1]
    float* hT_out  = out + (size_t)BATCH * TSTEPS * 3;      // [1,B,H]
    float* cT_out  = hT_out + BATCH * HIDDEN;               // [1,B,H]

    for (int t = 0; t < TSTEPS; ++t) {
        const int bsel = t & 1;
        const int slot = t & (CHUNK - 1);

        // Issue depth-2 prefetch FIRST (for step t+2), then compute with the
        // buffer filled at t-2. Clamp pointer advance at the tail.
        const ulonglong2 cur[4] = {xbuf[bsel][0], xbuf[bsel][1],
                                   xbuf[bsel][2], xbuf[bsel][3]};
        const float mk[4] = {mbuf[bsel][0], mbuf[bsel][1],
                             mbuf[bsel][2], mbuf[bsel][3]};
        {
            const int adv = (t < TSTEPS - 3) ? HIDDEN : 0;
            const int madv = (t < TSTEPS - 3) ? 1 : 0;
            #pragma unroll
            for (int s = 0; s < 4; ++s) {
                xbuf[bsel][s] = xp[s][0];
                mbuf[bsel][s] = mp[s][0];
                xp[s] += adv; mp[s] += madv;
            }
        }

        // Gates = xg + h @ W_hh (weights in registers, h broadcast from smem).
        ull aif[4], ago[4];
        #pragma unroll
        for (int s = 0; s < 4; ++s) { aif[s] = cur[s].x; ago[s] = cur[s].y; }

        #pragma unroll
        for (int k = 0; k < HIDDEN; ++k) {
            const ulonglong2* hr =
                reinterpret_cast<const ulonglong2*>(&sm.hq[bsel][k][0]);
            const ulonglong2 h01 = hr[0], h23 = hr[1];
            const ull wi = whh_if[k], wg = whh_go[k];
            aif[0] = fma2(h01.x, wi, aif[0]); ago[0] = fma2(h01.x, wg, ago[0]);
            aif[1] = fma2(h01.y, wi, aif[1]); ago[1] = fma2(h01.y, wg, ago[1]);
            aif[2] = fma2(h23.x, wi, aif[2]); ago[2] = fma2(h23.x, wg, ago[2]);
            aif[3] = fma2(h23.y, wi, aif[3]); ago[3] = fma2(h23.y, wg, ago[3]);
        }

        float hs[4];
        #pragma unroll
        for (int s = 0; s < 4; ++s) {
            const bool act = (mk[s] == 1.0f);
            const float2 g1 = unpack2(aif[s]), g2 = unpack2(ago[s]);
            const float cn = fmaf(sigf(g1.y), c[s], sigf(g1.x) * tanhap(g2.x));
            const float hn = sigf(g2.y) * tanhap(cn);
            c[s]  = act ? cn : c[s];
            h[s]  = act ? hn : h[s];
            hs[s] = act ? hn : 0.f;
        }

        {
            ulonglong2* hw = reinterpret_cast<ulonglong2*>(&sm.hq[bsel ^ 1][lane][0]);
            hw[0] = make_ulonglong2(dup2(h[0]), dup2(h[1]));
            hw[1] = make_ulonglong2(dup2(h[2]), dup2(h[3]));
        }
        sm.hist[slot][lane] = make_ulonglong2(pack2(hs[0], hs[1]), pack2(hs[2], hs[3]));
        __syncwarp();

        // Bulk head phase over the finished 16-step chunk.
        if (slot == CHUNK - 1) {
            const int tt = lane & 15;
            const int pr = lane >> 4;
            const ull* hrow = reinterpret_cast<const ull*>(&sm.hist[tt][0]) + pr;
            ull p0 = 0ULL, p1 = 0ULL, pl = 0ULL;
            #pragma unroll
            for (int j = 0; j < HIDDEN; ++j) {
                const ull hv = hrow[j * 2];
                p0 = fma2(hv, sm.wcd0[j], p0);
                p1 = fma2(hv, sm.wcd1[j], p1);
                pl = fma2(hv, sm.wcdl[j], pl);
            }
            const float2 q0 = unpack2(p0), q1 = unpack2(p1), ql = unpack2(pl);
            const int tg = t - (CHUNK - 1) + tt;
            const size_t oA = (size_t)(s0 + 2 * pr) * TSTEPS + tg;
            const size_t oB = oA + TSTEPS;
            reinterpret_cast<float2*>(pos_out)[oA] = make_float2(q0.x + cb0, q1.x + cb1);
            reinterpret_cast<float2*>(pos_out)[oB] = make_float2(q0.y + cb0, q1.y + cb1);
            lv_out[oA] = sigf(ql.x + blv);
            lv_out[oB] = sigf(ql.y + blv);
            __syncwarp();
        }
    }

    #pragma unroll
    for (int s = 0; s < 4; ++s) {
        hT_out[(s0 + s) * HIDDEN + lane] = h[s];
        cT_out[(s0 + s) * HIDDEN + lane] = c[s];
    }
}

extern "C" void kernel_launch(void* const* d_in, const int* in_sizes, int n_in,
                              void* d_out, int out_size)
{
    const float* x    = (const float*)d_in[0];
    const float* h0   = (const float*)d_in[1];
    const float* c0   = (const float*)d_in[2];
    const float* W_ih = (const float*)d_in[3];
    const float* W_hh = (const float*)d_in[4];
    const float* b_ih = (const float*)d_in[5];
    const float* b_hh = (const float*)d_in[6];
    const float* W_all= (const float*)d_in[7];
    const float* b_all= (const float*)d_in[8];
    const float* W_pos= (const float*)d_in[9];
    const float* b_pos= (const float*)d_in[10];
    const float* W_lv = (const float*)d_in[11];
    const float* b_lv = (const float*)d_in[12];
    float* out = (float*)d_out;

    xgate_kernel<<<BATCH, 256>>>(x, W_ih, b_ih, b_hh);
    lstm_rec_kernel<<<BATCH / 4, 32>>>(h0, c0, W_hh,
                                       W_all, b_all, W_pos, b_pos, W_lv, b_lv, out);
}

// round 17
// speedup vs baseline: 1.4407x; 1.1338x over previous
#include <cuda_runtime.h>

#define HIDDEN 32
#define FEAT 30
#define NK 29                 /* feature 29 (mask bit) folded into bias */
#define TSTEPS 512
#define BATCH 4096
#define CHUNK 16
#define K1TS 8                /* timesteps staged per K1 inner iter */
#define XROW 10               /* xsd ull row stride: 80B, 16B-aligned */
#define RING 5                /* K2 xg ring stages; fill distance 4 */
#define TSF (TSTEPS * FEAT)

typedef unsigned long long ull;
typedef unsigned int u32;

// Scratch: XG[b][t][j] = (if, go) fp32 gate partials (x-part + bias); mask[b][t].
__device__ ulonglong2 g_xg[(size_t)BATCH * TSTEPS * HIDDEN];
__device__ float g_mask[(size_t)BATCH * TSTEPS];

__device__ __forceinline__ float tanhap(float x) {
    float y; asm("tanh.approx.f32 %0, %1;" : "=f"(y) : "f"(x)); return y;
}
__device__ __forceinline__ float sigf(float x) {
    return fmaf(0.5f, tanhap(0.5f * x), 0.5f);
}
__device__ __forceinline__ ull fma2(ull a, ull b, ull c) {
    ull d;
    asm("fma.rn.f32x2 %0, %1, %2, %3;" : "=l"(d) : "l"(a), "l"(b), "l"(c));
    return d;
}
__device__ __forceinline__ ull pack2(float lo, float hi) {
    ull d; asm("mov.b64 %0, {%1, %2};" : "=l"(d) : "f"(lo), "f"(hi)); return d;
}
__device__ __forceinline__ ull dup2(float v) {
    ull d; asm("mov.b64 %0, {%1, %1};" : "=l"(d) : "f"(v)); return d;
}
__device__ __forceinline__ float2 unpack2(ull v) {
    float lo, hi; asm("mov.b64 {%0, %1}, %2;" : "=f"(lo), "=f"(hi) : "l"(v));
    return make_float2(lo, hi);
}
__device__ __forceinline__ void cpa16(u32 dst, const void* src) {
    asm volatile("cp.async.cg.shared.global [%0], [%1], 16;"
                 :: "r"(dst), "l"(src) : "memory");
}
__device__ __forceinline__ void cpa4(u32 dst, const void* src) {
    asm volatile("cp.async.ca.shared.global [%0], [%1], 4;"
                 :: "r"(dst), "l"(src) : "memory");
}
__device__ __forceinline__ void cpa_commit() {
    asm volatile("cp.async.commit_group;" ::: "memory");
}
__device__ __forceinline__ void cpa_wait3() {
    asm volatile("cp.async.wait_group 3;" ::: "memory");
}

// ========================== K1: dense x-gates ==============================
// Block = 8 warps, one sample. Register-capped so nothing spills;
// weights in conflict-free smem, amortized over 8 staged timesteps.
__global__ void __launch_bounds__(256, 3)
xgate_kernel(const float* __restrict__ x,
             const float* __restrict__ W_ih,
             const float* __restrict__ b_ih, const float* __restrict__ b_hh)
{
    __shared__ ulonglong2 sWih[NK][HIDDEN];   // [k][j]: 512B rows, conflict-free
    __shared__ ull xsd[8][NK][XROW];          // [warp][k][t] dup'd x values

    const int tid  = threadIdx.x;
    const int lane = tid & 31;
    const int wid  = tid >> 5;
    const int b    = blockIdx.x;

    for (int idx = tid; idx < NK * HIDDEN; idx += 256) {
        const int k = idx >> 5, j = idx & 31;
        sWih[k][j] = make_ulonglong2(
            pack2(W_ih[j * FEAT + k],        W_ih[(32 + j) * FEAT + k]),
            pack2(W_ih[(64 + j) * FEAT + k], W_ih[(96 + j) * FEAT + k]));
    }
    const ull bias_if = pack2(
        b_ih[lane]      + b_hh[lane]      + W_ih[lane * FEAT + 29],
        b_ih[32 + lane] + b_hh[32 + lane] + W_ih[(32 + lane) * FEAT + 29]);
    const ull bias_go = pack2(
        b_ih[64 + lane] + b_hh[64 + lane] + W_ih[(64 + lane) * FEAT + 29],
        b_ih[96 + lane] + b_hh[96 + lane] + W_ih[(96 + lane) * FEAT + 29]);
    __syncthreads();

    const float* xb = x + (size_t)b * TSF;

    #pragma unroll 1
    for (int iter = 0; iter < TSTEPS / (8 * K1TS); ++iter) {
        const int t0 = wid * (TSTEPS / 8) + iter * K1TS;

        #pragma unroll
        for (int r = 0; r < 8; ++r) {
            const int idx = r * 32 + lane;           // 0..255 (240 used)
            if (idx < K1TS * FEAT) {
                const int tr = idx / FEAT, k = idx % FEAT;
                const float v = xb[(size_t)t0 * FEAT + idx];
                if (k < NK) xsd[wid][k][tr] = dup2(v);
                else        g_mask[(size_t)b * TSTEPS + t0 + tr] = v;
            }
        }
        __syncwarp();

        ull aif[K1TS], ago[K1TS];
        #pragma unroll
        for (int t = 0; t < K1TS; ++t) { aif[t] = bias_if; ago[t] = bias_go; }

        #pragma unroll
        for (int k = 0; k < NK; ++k) {
            const ulonglong2 w = sWih[k][lane];
            const ulonglong2* xr =
                reinterpret_cast<const ulonglong2*>(&xsd[wid][k][0]);
            #pragma unroll
            for (int p = 0; p < K1TS / 2; ++p) {
                const ulonglong2 xp = xr[p];
                aif[2 * p]     = fma2(xp.x, w.x, aif[2 * p]);
                ago[2 * p]     = fma2(xp.x, w.y, ago[2 * p]);
                aif[2 * p + 1] = fma2(xp.y, w.x, aif[2 * p + 1]);
                ago[2 * p + 1] = fma2(xp.y, w.y, ago[2 * p + 1]);
            }
        }
        #pragma unroll
        for (int t = 0; t < K1TS; ++t)
            g_xg[((size_t)b * TSTEPS + t0 + t) * HIDDEN + lane] =
                make_ulonglong2(aif[t], ago[t]);
        __syncwarp();
    }
}

// ========================== K2: recurrence (cp.async ring) =================
struct __align__(16) Smem2 {
    ulonglong2 ring[RING][4][HIDDEN];  // [stage][sample][lane] xg; 10 KB
    float      mring[RING][4];         // [stage][sample] masks; 16B rows
    ull hq[2][HIDDEN][6];              // [buf][k][s+pad] dup'd h; 48B rows
    ulonglong2 hist[CHUNK][33];        // [slot][j] masked-h pairs, padded
    ull wcd0[HIDDEN], wcd1[HIDDEN], wcdl[HIDDEN];
};

__global__ void __launch_bounds__(32)
lstm_rec_kernel(const float* __restrict__ h0, const float* __restrict__ c0,
                const float* __restrict__ W_hh,
                const float* __restrict__ W_all, const float* __restrict__ b_all,
                const float* __restrict__ W_pos, const float* __restrict__ b_pos,
                const float* __restrict__ W_lv, const float* __restrict__ b_lv,
                float* __restrict__ out)
{
    __shared__ Smem2 sm;
    const int lane = threadIdx.x;
    const int s0 = blockIdx.x * 4;

    ull whh_if[HIDDEN], whh_go[HIDDEN];   // register-resident
    #pragma unroll
    for (int k = 0; k < HIDDEN; ++k) {
        whh_if[k] = pack2(W_hh[lane * HIDDEN + k],        W_hh[(32 + lane) * HIDDEN + k]);
        whh_go[k] = pack2(W_hh[(64 + lane) * HIDDEN + k], W_hh[(96 + lane) * HIDDEN + k]);
    }
    // Folded heads: wc = W_pos @ W_all, cb = W_pos @ b_all + b_pos.
    float wc0 = 0.f, wc1 = 0.f, cb0 = b_pos[0], cb1 = b_pos[1];
    #pragma unroll
    for (int m = 0; m < HIDDEN; ++m) {
        const float wa = W_all[m * HIDDEN + lane];
        wc0 = fmaf(W_pos[m],      wa, wc0);
        wc1 = fmaf(W_pos[32 + m], wa, wc1);
        cb0 = fmaf(W_pos[m],      b_all[m], cb0);
        cb1 = fmaf(W_pos[32 + m], b_all[m], cb1);
    }
    sm.wcd0[lane] = dup2(wc0);
    sm.wcd1[lane] = dup2(wc1);
    sm.wcdl[lane] = dup2(W_lv[lane]);
    const float blv = b_lv[0];

    float h[4], c[4];
    #pragma unroll
    for (int s = 0; s < 4; ++s) {
        h[s] = h0[(s0 + s) * HIDDEN + lane];
        c[s] = c0[(s0 + s) * HIDDEN + lane];
    }
    {
        ulonglong2* hw = reinterpret_cast<ulonglong2*>(&sm.hq[0][lane][0]);
        hw[0] = make_ulonglong2(dup2(h[0]), dup2(h[1]));
        hw[1] = make_ulonglong2(dup2(h[2]), dup2(h[3]));
    }

    // Streaming gmem pointers for the ring fill (advance 1 step per iter).
    const char* xsrc = reinterpret_cast<const char*>(
        g_xg + (size_t)s0 * TSTEPS * HIDDEN + lane);
    const char* msrc = (lane < 4)
        ? reinterpret_cast<const char*>(g_mask + (size_t)(s0 + lane) * TSTEPS)
        : reinterpret_cast<const char*>(g_mask);
    const u32 ring0 = (u32)__cvta_generic_to_shared(&sm.ring[0][0][lane]);
    const u32 mring0 = (u32)__cvta_generic_to_shared(&sm.mring[0][0]);

    // Prologue: fill steps 0..3 into stages 0..3 (4 groups).
    #pragma unroll
    for (int st = 0; st < 4; ++st) {
        #pragma unroll
        for (int s = 0; s < 4; ++s)
            cpa16(ring0 + st * (4 * HIDDEN * 16) + s * (HIDDEN * 16),
                  xsrc + ((size_t)s * TSTEPS + st) * (HIDDEN * 16));
        if (lane < 4) cpa4(mring0 + st * 16 + lane * 4, msrc + st * 4);
        cpa_commit();
    }
    __syncwarp();

    float* pos_out = out;                                   // [B,T,2]
    float* lv_out  = out + (size_t)BATCH * TSTEPS * 2;      // [B,T,1]
    float* hT_out  = out + (size_t)BATCH * TSTEPS * 3;      // [1,B,H]
    float* cT_out  = hT_out + BATCH * HIDDEN;               // [1,B,H]

    int rc = 0;                 // t % RING (consume stage)
    int rf = 4;                 // (t+4) % RING (fill stage)
    for (int t = 0; t < TSTEPS; ++t) {
        const int bsel = t & 1;
        const int slot = t & (CHUNK - 1);

        // Wait for this step's fill; syncwarp for cross-lane mask visibility.
        cpa_wait3();
        __syncwarp();

        ulonglong2 cur[4];
        #pragma unroll
        for (int s = 0; s < 4; ++s) cur[s] = sm.ring[rc][s][lane];
        const float4 mk4 = *reinterpret_cast<const float4*>(&sm.mring[rc][0]);
        const float mk[4] = {mk4.x, mk4.y, mk4.z, mk4.w};

        // Issue fill for step t+4 (empty commit at the tail keeps group count).
        if (t + 4 < TSTEPS) {
            #pragma unroll
            for (int s = 0; s < 4; ++s)
                cpa16(ring0 + rf * (4 * HIDDEN * 16) + s * (HIDDEN * 16),
                      xsrc + ((size_t)s * TSTEPS + t + 4) * (HIDDEN * 16));
            if (lane < 4) cpa4(mring0 + rf * 16 + lane * 4, msrc + (t + 4) * 4);
        }
        cpa_commit();

        // Gates = xg + h @ W_hh (weights in registers, h broadcast from smem).
        ull aif[4], ago[4];
        #pragma unroll
        for (int s = 0; s < 4; ++s) { aif[s] = cur[s].x; ago[s] = cur[s].y; }

        #pragma unroll
        for (int k = 0; k < HIDDEN; ++k) {
            const ulonglong2* hr =
                reinterpret_cast<const ulonglong2*>(&sm.hq[bsel][k][0]);
            const ulonglong2 h01 = hr[0], h23 = hr[1];
            const ull wi = whh_if[k], wg = whh_go[k];
            aif[0] = fma2(h01.x, wi, aif[0]); ago[0] = fma2(h01.x, wg, ago[0]);
            aif[1] = fma2(h01.y, wi, aif[1]); ago[1] = fma2(h01.y, wg, ago[1]);
            aif[2] = fma2(h23.x, wi, aif[2]); ago[2] = fma2(h23.x, wg, ago[2]);
            aif[3] = fma2(h23.y, wi, aif[3]); ago[3] = fma2(h23.y, wg, ago[3]);
        }

        float hs[4];
        #pragma unroll
        for (int s = 0; s < 4; ++s) {
            const bool act = (mk[s] == 1.0f);
            const float2 g1 = unpack2(aif[s]), g2 = unpack2(ago[s]);
            const float cn = fmaf(sigf(g1.y), c[s], sigf(g1.x) * tanhap(g2.x));
            const float hn = sigf(g2.y) * tanhap(cn);
            c[s]  = act ? cn : c[s];
            h[s]  = act ? hn : h[s];
            hs[s] = act ? hn : 0.f;
        }

        {
            ulonglong2* hw = reinterpret_cast<ulonglong2*>(&sm.hq[bsel ^ 1][lane][0]);
            hw[0] = make_ulonglong2(dup2(h[0]), dup2(h[1]));
            hw[1] = make_ulonglong2(dup2(h[2]), dup2(h[3]));
        }
        sm.hist[slot][lane] = make_ulonglong2(pack2(hs[0], hs[1]), pack2(hs[2], hs[3]));
        __syncwarp();

        // Bulk head phase over the finished 16-step chunk.
        if (slot == CHUNK - 1) {
            const int tt = lane & 15;
            const int pr = lane >> 4;
            const ull* hrow = reinterpret_cast<const ull*>(&sm.hist[tt][0]) + pr;
            ull p0 = 0ULL, p1 = 0ULL, pl = 0ULL;
            #pragma unroll
            for (int j = 0; j < HIDDEN; ++j) {
                const ull hv = hrow[j * 2];
                p0 = fma2(hv, sm.wcd0[j], p0);
                p1 = fma2(hv, sm.wcd1[j], p1);
                pl = fma2(hv, sm.wcdl[j], pl);
            }
            const float2 q0 = unpack2(p0), q1 = unpack2(p1), ql = unpack2(pl);
            const int tg = t - (CHUNK - 1) + tt;
            const size_t oA = (size_t)(s0 + 2 * pr) * TSTEPS + tg;
            const size_t oB = oA + TSTEPS;
            reinterpret_cast<float2*>(pos_out)[oA] = make_float2(q0.x + cb0, q1.x + cb1);
            reinterpret_cast<float2*>(pos_out)[oB] = make_float2(q0.y + cb0, q1.y + cb1);
            lv_out[oA] = sigf(ql.x + blv);
            lv_out[oB] = sigf(ql.y + blv);
            __syncwarp();
        }

        rc = (rc + 1 == RING) ? 0 : rc + 1;
        rf = (rf + 1 == RING) ? 0 : rf + 1;
    }

    #pragma unroll
    for (int s = 0; s < 4; ++s) {
        hT_out[(s0 + s) * HIDDEN + lane] = h[s];
        cT_out[(s0 + s) * HIDDEN + lane] = c[s];
    }
}

extern "C" void kernel_launch(void* const* d_in, const int* in_sizes, int n_in,
                              void* d_out, int out_size)
{
    const float* x    = (const float*)d_in[0];
    const float* h0   = (const float*)d_in[1];
    const float* c0   = (const float*)d_in[2];
    const float* W_ih = (const float*)d_in[3];
    const float* W_hh = (const float*)d_in[4];
    const float* b_ih = (const float*)d_in[5];
    const float* b_hh = (const float*)d_in[6];
    const float* W_all= (const float*)d_in[7];
    const float* b_all= (const float*)d_in[8];
    const float* W_pos= (const float*)d_in[9];
    const float* b_pos= (const float*)d_in[10];
    const float* W_lv = (const float*)d_in[11];
    const float* b_lv = (const float*)d_in[12];
    float* out = (float*)d_out;

    xgate_kernel<<<BATCH, 256>>>(x, W_ih, b_ih, b_hh);
    lstm_rec_kernel<<<BATCH / 4, 32>>>(h0, c0, W_hh,
                                       W_all, b_all, W_pos, b_pos, W_lv, b_lv, out);
}